// round 13
// baseline (speedup 1.0000x reference)
#include <cuda_runtime.h>
#include <math.h>

// Problem constants (B,T,D,U) = (256, 1024, 128, 256)
#define RNN_B 256
#define RNN_T 1024
#define RNN_D 128
#define RNN_U 256

// Scan K-quarter split: per quarter (64 rows), 48 rows of Wh in registers,
// 16 rows streamed from L1 (LDG, resident after step 0).
#define KREG 48
#define KLDG 16

typedef unsigned long long u64;

// ---------------------------------------------------------------------------
// Packed fp32x2 helpers (Blackwell FFMA2 path — only reachable via PTX)
// ---------------------------------------------------------------------------
__device__ __forceinline__ u64 ffma2(u64 a, u64 b, u64 c) {
    u64 d;
    asm("fma.rn.f32x2 %0, %1, %2, %3;" : "=l"(d) : "l"(a), "l"(b), "l"(c));
    return d;
}
__device__ __forceinline__ u64 fadd2(u64 a, u64 b) {
    u64 d;
    asm("add.rn.f32x2 %0, %1, %2;" : "=l"(d) : "l"(a), "l"(b));
    return d;
}
__device__ __forceinline__ u64 pack2(float x, float y) {
    u64 r;
    asm("mov.b64 %0, {%1, %2};" : "=l"(r) : "f"(x), "f"(y));
    return r;
}
__device__ __forceinline__ void unpack2(u64 v, float& x, float& y) {
    asm("mov.b64 {%0, %1}, %2;" : "=f"(x), "=f"(y) : "l"(v));
}

// Fast accurate-enough tanh: 1 - 2/(e^{2x}+1). Saturates correctly for |x|
// large. Error ~1e-6, far inside the 1e-3 gate.
__device__ __forceinline__ float tanh_fast(float x) {
    float e = __expf(2.0f * x);
    return 1.0f - 2.0f / (e + 1.0f);
}

// ---------------------------------------------------------------------------
// Kernel 1: x_proj = x @ Wx + bias -> d_out (scan overwrites in place).
// 256 threads/CTA, occupancy 2 (32 KB smem tile), tile = 32 (b*t) rows.
//   g = tid>>6: row subgroup (8 rows), p = tid&63: u-quad (u = 4p..4p+3).
// x staged in smem duplicated {v,v}; each broadcast LDS.128 yields two
// dup-pairs (1 crossbar phase) feeding 4 FFMA2. Wx via L2/L1-resident LDG.
// ---------------------------------------------------------------------------
__global__ __launch_bounds__(256, 2) void xproj_kernel(
        const float* __restrict__ x, const float* __restrict__ W,
        const float* __restrict__ bias, float* __restrict__ out) {
    __shared__ u64 sx[32 * RNN_D];               // 32 KB, duplicated x tile

    const int tid = threadIdx.x;
    const int g = tid >> 6;                      // row subgroup 0..3 (8 rows)
    const int p = tid & 63;                      // u-quad index
    const size_t r0 = (size_t)blockIdx.x * 32;   // first (b*t) row of tile

    // Stage x tile, duplicated into both f32x2 lanes (coalesced LDG).
    for (int idx = tid; idx < 32 * RNN_D; idx += 256) {
        int r = idx >> 7;
        int d = idx & 127;
        float v = x[(r0 + r) * RNN_D + d];
        sx[idx] = pack2(v, v);
    }
    __syncthreads();

    ulonglong2 b2 = *reinterpret_cast<const ulonglong2*>(bias + 4 * p);
    u64 acc0[8], acc1[8];
#pragma unroll
    for (int r = 0; r < 8; r++) { acc0[r] = b2.x; acc1[r] = b2.y; }

    // Wx = W[U:], row-major (D rows of U floats).
    const float* wp = W + (size_t)RNN_U * RNN_U + 4 * p;
    const u64* sxg = sx + (g * 8) * RNN_D;       // this subgroup's 8 rows

#pragma unroll 4
    for (int d = 0; d < RNN_D; d += 2) {
        ulonglong2 w0 = __ldg(reinterpret_cast<const ulonglong2*>(
            wp + (size_t)d * RNN_U));
        ulonglong2 w1 = __ldg(reinterpret_cast<const ulonglong2*>(
            wp + (size_t)(d + 1) * RNN_U));
#pragma unroll
        for (int r = 0; r < 8; r++) {
            ulonglong2 xv = *reinterpret_cast<const ulonglong2*>(
                sxg + r * RNN_D + d);            // {x[r][d]dup, x[r][d+1]dup}
            acc0[r] = ffma2(w0.x, xv.x, acc0[r]);
            acc1[r] = ffma2(w0.y, xv.x, acc1[r]);
            acc0[r] = ffma2(w1.x, xv.y, acc0[r]);
            acc1[r] = ffma2(w1.y, xv.y, acc1[r]);
        }
    }

#pragma unroll
    for (int r = 0; r < 8; r++)
        *reinterpret_cast<ulonglong2*>(
            out + (r0 + g * 8 + r) * RNN_U + 4 * p) =
            make_ulonglong2(acc0[r], acc1[r]);
}

// ---------------------------------------------------------------------------
// Kernel 2: persistent batch-parallel scan. 128 CTAs, 2 batches each, 256 thr.
//   s = tid>>6 : K-quarter (k in [64s, 64s+64))
//   p = tid&63 : u-quad, output pairs 2p, 2p+1 (over the quarter's K-slice)
// Wh rows [64s, 64s+48) in registers (96 u64/thread); rows [64s+48, 64s+64)
// via LDG (L1-resident after first step — off the smem crossbar entirely).
// h kept duplicated {h,h}; each broadcast LDS.128 = two dup-pairs, 1 phase.
//
// Per step: MAC over K-quarter -> publish partials to parity-buffered sred ->
// full __syncthreads -> distributed finalize (EVERY thread reduces ONE output
// pair: group s owns h-slice [64s,64s+64), which only group s reads next
// step) -> group-local named barrier (64 threads) -> next step.
// ---------------------------------------------------------------------------
__global__ __launch_bounds__(256, 1) void rnn_scan_kernel(
        const float* __restrict__ W, const float* __restrict__ h0,
        float* __restrict__ out) {
    __shared__ u64 sh[2 * RNN_U];          // [batch][u] duplicated h (4 KB)
    __shared__ u64 sred[2 * 2 * 4 * 128];  // [parity][batch][quarter][pair] (16 KB)

    const int tid = threadIdx.x;
    const int s = tid >> 6;                // K-quarter
    const int p = tid & 63;                // u-quad
    const int b0 = blockIdx.x * 2;

    // --- register-resident Wh: k = 64s + j, j in [0,KREG); 2 u64/row ---
    u64 wr0[KREG], wr1[KREG];
    {
        const float* wb = W + (size_t)(64 * s) * RNN_U + 4 * p;
#pragma unroll
        for (int j = 0; j < KREG; j++) {
            ulonglong2 w = *reinterpret_cast<const ulonglong2*>(
                wb + (size_t)j * RNN_U);
            wr0[j] = w.x;
            wr1[j] = w.y;
        }
    }
    const float* wtail = W + (size_t)(64 * s + KREG) * RNN_U + 4 * p;

    // --- initial h from h0 (duplicated lanes) ---
    for (int idx = tid; idx < 2 * RNN_U; idx += 256) {
        int b = idx >> 8;
        int u = idx & 255;
        float h = h0[(size_t)(b0 + b) * RNN_U + u];
        sh[idx] = pack2(h, h);
    }
    __syncthreads();

    const u64* sh0 = sh + 64 * s;          // batch 0 h slice for this quarter
    const u64* sh1 = sh + RNN_U + 64 * s;  // batch 1

    // Finalize task: this thread reduces output pair fpp for batch fb.
    const int fb  = p >> 5;
    const int fpp = 32 * s + (p & 31);     // global pair index 0..127
    float* fout = out + (size_t)(b0 + fb) * RNN_T * RNN_U + 2 * fpp;
    u64* fsh = &sh[fb * RNN_U + 2 * fpp];

    for (int t = 0; t < RNN_T; t++) {
        const int buf = t & 1;

        // Prefetch this step's x_proj for the finalize task (hidden by MACs).
        u64 xp = *reinterpret_cast<const u64*>(fout + (size_t)t * RNN_U);

        u64 a00 = 0, a01 = 0, a10 = 0, a11 = 0;  // [pair][batch]

        // LDG-weight MACs first (loads issued early, L1-resident).
#pragma unroll
        for (int j = 0; j < KLDG; j += 2) {
            ulonglong2 w0 = __ldg(reinterpret_cast<const ulonglong2*>(
                wtail + (size_t)j * RNN_U));
            ulonglong2 w1 = __ldg(reinterpret_cast<const ulonglong2*>(
                wtail + (size_t)(j + 1) * RNN_U));
            ulonglong2 hb0 = *reinterpret_cast<const ulonglong2*>(sh0 + KREG + j);
            ulonglong2 hb1 = *reinterpret_cast<const ulonglong2*>(sh1 + KREG + j);
            a00 = ffma2(w0.x, hb0.x, a00);
            a01 = ffma2(w0.y, hb0.x, a01);
            a10 = ffma2(w0.x, hb1.x, a10);
            a11 = ffma2(w0.y, hb1.x, a11);
            a00 = ffma2(w1.x, hb0.y, a00);
            a01 = ffma2(w1.y, hb0.y, a01);
            a10 = ffma2(w1.x, hb1.y, a10);
            a11 = ffma2(w1.y, hb1.y, a11);
        }
        // Register-weight MACs: 48 rows, 2 batches, 2 pairs.
#pragma unroll
        for (int j = 0; j < KREG; j += 2) {
            ulonglong2 hb0 = *reinterpret_cast<const ulonglong2*>(sh0 + j);
            ulonglong2 hb1 = *reinterpret_cast<const ulonglong2*>(sh1 + j);
            a00 = ffma2(wr0[j],     hb0.x, a00);
            a01 = ffma2(wr1[j],     hb0.x, a01);
            a10 = ffma2(wr0[j],     hb1.x, a10);
            a11 = ffma2(wr1[j],     hb1.x, a11);
            a00 = ffma2(wr0[j + 1], hb0.y, a00);
            a01 = ffma2(wr1[j + 1], hb0.y, a01);
            a10 = ffma2(wr0[j + 1], hb1.y, a10);
            a11 = ffma2(wr1[j + 1], hb1.y, a11);
        }

        // Publish partials (parity-buffered: no cross-step WAR on sred).
        *reinterpret_cast<ulonglong2*>(
            &sred[((buf * 2 + 0) * 4 + s) * 128 + 2 * p]) =
            make_ulonglong2(a00, a01);
        *reinterpret_cast<ulonglong2*>(
            &sred[((buf * 2 + 1) * 4 + s) * 128 + 2 * p]) =
            make_ulonglong2(a10, a11);
        __syncthreads();   // all partials visible; all sh reads complete

        // Distributed finalize: every thread reduces its one output pair.
        {
            const u64* rb = &sred[(buf * 2 + fb) * 4 * 128 + fpp];
            u64 z = fadd2(fadd2(rb[0], rb[128]), fadd2(rb[256], rb[384]));
            z = fadd2(z, xp);
            float f0, f1;
            unpack2(z, f0, f1);
            f0 = tanh_fast(f0);
            f1 = tanh_fast(f1);
            // Output (overwrites x_proj slot for this t, in place).
            *reinterpret_cast<u64*>(fout + (size_t)t * RNN_U) = pack2(f0, f1);
            // Refresh duplicated h for the slice only THIS group reads.
            *reinterpret_cast<ulonglong2*>(fsh) =
                make_ulonglong2(pack2(f0, f0), pack2(f1, f1));
        }
        // Group-local barrier: only group s consumes the h-slice it wrote.
        asm volatile("bar.sync %0, %1;" :: "r"(s + 1), "r"(64) : "memory");
    }
}

// ---------------------------------------------------------------------------
// Launch: x_proj fills d_out, then the scan rewrites it in place.
// Inputs (metadata order): x, h0, W, bias. Output dtype float32.
// ---------------------------------------------------------------------------
extern "C" void kernel_launch(void* const* d_in, const int* in_sizes, int n_in,
                              void* d_out, int out_size) {
    const float* x    = (const float*)d_in[0];
    const float* h0   = (const float*)d_in[1];
    const float* W    = (const float*)d_in[2];
    const float* bias = (const float*)d_in[3];
    float* out = (float*)d_out;

    xproj_kernel<<<(RNN_B * RNN_T) / 32, 256>>>(x, W, bias, out);
    rnn_scan_kernel<<<RNN_B / 2, 256>>>(W, h0, out);
}

// round 14
// speedup vs baseline: 1.0063x; 1.0063x over previous
#include <cuda_runtime.h>
#include <math.h>

// Problem constants (B,T,D,U) = (256, 1024, 128, 256)
#define RNN_B 256
#define RNN_T 1024
#define RNN_D 128
#define RNN_U 256

// Scan K-quarter split: per quarter (64 rows), 48 rows of Wh in registers,
// 16 rows streamed from L1 (LDG, resident after step 0).
#define KREG 48
#define KLDG 16

typedef unsigned long long u64;

// ---------------------------------------------------------------------------
// Packed fp32x2 helpers (Blackwell FFMA2 path — only reachable via PTX)
// ---------------------------------------------------------------------------
__device__ __forceinline__ u64 ffma2(u64 a, u64 b, u64 c) {
    u64 d;
    asm("fma.rn.f32x2 %0, %1, %2, %3;" : "=l"(d) : "l"(a), "l"(b), "l"(c));
    return d;
}
__device__ __forceinline__ u64 fadd2(u64 a, u64 b) {
    u64 d;
    asm("add.rn.f32x2 %0, %1, %2;" : "=l"(d) : "l"(a), "l"(b));
    return d;
}
__device__ __forceinline__ u64 pack2(float x, float y) {
    u64 r;
    asm("mov.b64 %0, {%1, %2};" : "=l"(r) : "f"(x), "f"(y));
    return r;
}
__device__ __forceinline__ void unpack2(u64 v, float& x, float& y) {
    asm("mov.b64 {%0, %1}, %2;" : "=f"(x), "=f"(y) : "l"(v));
}

// Fast accurate-enough tanh: 1 - 2/(e^{2x}+1). Saturates correctly for |x|
// large. Error ~1e-6, far inside the 1e-3 gate.
__device__ __forceinline__ float tanh_fast(float x) {
    float e = __expf(2.0f * x);
    return 1.0f - 2.0f / (e + 1.0f);
}

// ---------------------------------------------------------------------------
// Kernel 1: x_proj = x @ Wx + bias -> d_out (scan overwrites in place).
// 256 threads/CTA, occupancy 2 (32 KB smem tile), tile = 32 (b*t) rows.
//   g = tid>>6: row subgroup (8 rows), p = tid&63: u-quad (u = 4p..4p+3).
// x staged in smem duplicated {v,v}; each broadcast LDS.128 yields two
// dup-pairs (1 crossbar phase) feeding 4 FFMA2. Wx via L2/L1-resident LDG.
// ---------------------------------------------------------------------------
__global__ __launch_bounds__(256, 2) void xproj_kernel(
        const float* __restrict__ x, const float* __restrict__ W,
        const float* __restrict__ bias, float* __restrict__ out) {
    __shared__ u64 sx[32 * RNN_D];               // 32 KB, duplicated x tile

    const int tid = threadIdx.x;
    const int g = tid >> 6;                      // row subgroup 0..3 (8 rows)
    const int p = tid & 63;                      // u-quad index
    const size_t r0 = (size_t)blockIdx.x * 32;   // first (b*t) row of tile

    // Stage x tile, duplicated into both f32x2 lanes (coalesced LDG).
    for (int idx = tid; idx < 32 * RNN_D; idx += 256) {
        int r = idx >> 7;
        int d = idx & 127;
        float v = x[(r0 + r) * RNN_D + d];
        sx[idx] = pack2(v, v);
    }
    __syncthreads();

    ulonglong2 b2 = *reinterpret_cast<const ulonglong2*>(bias + 4 * p);
    u64 acc0[8], acc1[8];
#pragma unroll
    for (int r = 0; r < 8; r++) { acc0[r] = b2.x; acc1[r] = b2.y; }

    // Wx = W[U:], row-major (D rows of U floats).
    const float* wp = W + (size_t)RNN_U * RNN_U + 4 * p;
    const u64* sxg = sx + (g * 8) * RNN_D;       // this subgroup's 8 rows

#pragma unroll 4
    for (int d = 0; d < RNN_D; d += 2) {
        ulonglong2 w0 = __ldg(reinterpret_cast<const ulonglong2*>(
            wp + (size_t)d * RNN_U));
        ulonglong2 w1 = __ldg(reinterpret_cast<const ulonglong2*>(
            wp + (size_t)(d + 1) * RNN_U));
#pragma unroll
        for (int r = 0; r < 8; r++) {
            ulonglong2 xv = *reinterpret_cast<const ulonglong2*>(
                sxg + r * RNN_D + d);            // {x[r][d]dup, x[r][d+1]dup}
            acc0[r] = ffma2(w0.x, xv.x, acc0[r]);
            acc1[r] = ffma2(w0.y, xv.x, acc1[r]);
            acc0[r] = ffma2(w1.x, xv.y, acc0[r]);
            acc1[r] = ffma2(w1.y, xv.y, acc1[r]);
        }
    }

#pragma unroll
    for (int r = 0; r < 8; r++)
        *reinterpret_cast<ulonglong2*>(
            out + (r0 + g * 8 + r) * RNN_U + 4 * p) =
            make_ulonglong2(acc0[r], acc1[r]);
}

// ---------------------------------------------------------------------------
// Kernel 2: persistent batch-parallel scan. 128 CTAs, 2 batches each, 256 thr.
//   s = tid>>6 : K-quarter (k in [64s, 64s+64))
//   p = tid&63 : u-quad, output pairs 2p, 2p+1 (over the quarter's K-slice)
// Wh rows [64s, 64s+48) in registers (96 u64/thread); rows [64s+48, 64s+64)
// via LDG (L1-resident after first step — off the smem crossbar entirely).
// h kept duplicated {h,h}; each broadcast LDS.128 = two dup-pairs, 1 phase.
//
// Per step: MAC over K-quarter -> publish partials to parity-buffered sred ->
// full __syncthreads -> distributed finalize (EVERY thread reduces ONE output
// pair: group s owns h-slice [64s,64s+64), which only group s reads next
// step) -> group-local named barrier (64 threads) -> next step.
// ---------------------------------------------------------------------------
__global__ __launch_bounds__(256, 1) void rnn_scan_kernel(
        const float* __restrict__ W, const float* __restrict__ h0,
        float* __restrict__ out) {
    __shared__ u64 sh[2 * RNN_U];          // [batch][u] duplicated h (4 KB)
    __shared__ u64 sred[2 * 2 * 4 * 128];  // [parity][batch][quarter][pair] (16 KB)

    const int tid = threadIdx.x;
    const int s = tid >> 6;                // K-quarter
    const int p = tid & 63;                // u-quad
    const int b0 = blockIdx.x * 2;

    // --- register-resident Wh: k = 64s + j, j in [0,KREG); 2 u64/row ---
    u64 wr0[KREG], wr1[KREG];
    {
        const float* wb = W + (size_t)(64 * s) * RNN_U + 4 * p;
#pragma unroll
        for (int j = 0; j < KREG; j++) {
            ulonglong2 w = *reinterpret_cast<const ulonglong2*>(
                wb + (size_t)j * RNN_U);
            wr0[j] = w.x;
            wr1[j] = w.y;
        }
    }
    const float* wtail = W + (size_t)(64 * s + KREG) * RNN_U + 4 * p;

    // --- initial h from h0 (duplicated lanes) ---
    for (int idx = tid; idx < 2 * RNN_U; idx += 256) {
        int b = idx >> 8;
        int u = idx & 255;
        float h = h0[(size_t)(b0 + b) * RNN_U + u];
        sh[idx] = pack2(h, h);
    }
    __syncthreads();

    const u64* sh0 = sh + 64 * s;          // batch 0 h slice for this quarter
    const u64* sh1 = sh + RNN_U + 64 * s;  // batch 1

    // Finalize task: this thread reduces output pair fpp for batch fb.
    const int fb  = p >> 5;
    const int fpp = 32 * s + (p & 31);     // global pair index 0..127
    float* fout = out + (size_t)(b0 + fb) * RNN_T * RNN_U + 2 * fpp;
    u64* fsh = &sh[fb * RNN_U + 2 * fpp];

    for (int t = 0; t < RNN_T; t++) {
        const int buf = t & 1;

        // Prefetch this step's x_proj for the finalize task (hidden by MACs).
        u64 xp = *reinterpret_cast<const u64*>(fout + (size_t)t * RNN_U);

        u64 a00 = 0, a01 = 0, a10 = 0, a11 = 0;  // [pair][batch]

        // LDG-weight MACs first (loads issued early, L1-resident).
#pragma unroll
        for (int j = 0; j < KLDG; j += 2) {
            ulonglong2 w0 = __ldg(reinterpret_cast<const ulonglong2*>(
                wtail + (size_t)j * RNN_U));
            ulonglong2 w1 = __ldg(reinterpret_cast<const ulonglong2*>(
                wtail + (size_t)(j + 1) * RNN_U));
            ulonglong2 hb0 = *reinterpret_cast<const ulonglong2*>(sh0 + KREG + j);
            ulonglong2 hb1 = *reinterpret_cast<const ulonglong2*>(sh1 + KREG + j);
            a00 = ffma2(w0.x, hb0.x, a00);
            a01 = ffma2(w0.y, hb0.x, a01);
            a10 = ffma2(w0.x, hb1.x, a10);
            a11 = ffma2(w0.y, hb1.x, a11);
            a00 = ffma2(w1.x, hb0.y, a00);
            a01 = ffma2(w1.y, hb0.y, a01);
            a10 = ffma2(w1.x, hb1.y, a10);
            a11 = ffma2(w1.y, hb1.y, a11);
        }
        // Register-weight MACs: 48 rows, 2 batches, 2 pairs.
#pragma unroll
        for (int j = 0; j < KREG; j += 2) {
            ulonglong2 hb0 = *reinterpret_cast<const ulonglong2*>(sh0 + j);
            ulonglong2 hb1 = *reinterpret_cast<const ulonglong2*>(sh1 + j);
            a00 = ffma2(wr0[j],     hb0.x, a00);
            a01 = ffma2(wr1[j],     hb0.x, a01);
            a10 = ffma2(wr0[j],     hb1.x, a10);
            a11 = ffma2(wr1[j],     hb1.x, a11);
            a00 = ffma2(wr0[j + 1], hb0.y, a00);
            a01 = ffma2(wr1[j + 1], hb0.y, a01);
            a10 = ffma2(wr0[j + 1], hb1.y, a10);
            a11 = ffma2(wr1[j + 1], hb1.y, a11);
        }

        // Publish partials (parity-buffered: no cross-step WAR on sred).
        *reinterpret_cast<ulonglong2*>(
            &sred[((buf * 2 + 0) * 4 + s) * 128 + 2 * p]) =
            make_ulonglong2(a00, a01);
        *reinterpret_cast<ulonglong2*>(
            &sred[((buf * 2 + 1) * 4 + s) * 128 + 2 * p]) =
            make_ulonglong2(a10, a11);
        __syncthreads();   // all partials visible; all sh reads complete

        // Distributed finalize: every thread reduces its one output pair.
        {
            const u64* rb = &sred[(buf * 2 + fb) * 4 * 128 + fpp];
            u64 z = fadd2(fadd2(rb[0], rb[128]), fadd2(rb[256], rb[384]));
            z = fadd2(z, xp);
            float f0, f1;
            unpack2(z, f0, f1);
            f0 = tanh_fast(f0);
            f1 = tanh_fast(f1);
            // Output (overwrites x_proj slot for this t, in place).
            *reinterpret_cast<u64*>(fout + (size_t)t * RNN_U) = pack2(f0, f1);
            // Refresh duplicated h for the slice only THIS group reads.
            *reinterpret_cast<ulonglong2*>(fsh) =
                make_ulonglong2(pack2(f0, f0), pack2(f1, f1));
        }
        // Group-local barrier: only group s consumes the h-slice it wrote.
        asm volatile("bar.sync %0, %1;" :: "r"(s + 1), "r"(64) : "memory");
    }
}

// ---------------------------------------------------------------------------
// Launch: x_proj fills d_out, then the scan rewrites it in place.
// Inputs (metadata order): x, h0, W, bias. Output dtype float32.
// ---------------------------------------------------------------------------
extern "C" void kernel_launch(void* const* d_in, const int* in_sizes, int n_in,
                              void* d_out, int out_size) {
    const float* x    = (const float*)d_in[0];
    const float* h0   = (const float*)d_in[1];
    const float* W    = (const float*)d_in[2];
    const float* bias = (const float*)d_in[3];
    float* out = (float*)d_out;

    xproj_kernel<<<(RNN_B * RNN_T) / 32, 256>>>(x, W, bias, out);
    rnn_scan_kernel<<<RNN_B / 2, 256>>>(W, h0, out);
}